// round 5
// baseline (speedup 1.0000x reference)
#include <cuda_runtime.h>

#define BB   256
#define SS   1024
#define HH   512
#define CC   10
#define CPG  8           // CTAs per cluster/group
#define BPG  16          // batch rows per group
#define JPC  64          // j rows per CTA
#define THREADS 256
#define K4   128         // HH/4
#define XCHUNK 64
#define HPAD 516         // padded h_s row stride (floats)
#define RPAD 68          // padded red row stride (floats)
#define WPH_LD 516

// shared memory layout (float offsets)
#define OFF_W4   0                          // [128][64] float4 = 32768 f (128 KB)
#define OFF_H    32768                      // h_s [16][516]  = 8256 f
#define OFF_RED  (OFF_H + BPG * HPAD)       // red [4][16][68] = 4352 f
#define OFF_WPH  (OFF_RED + 4 * BPG * RPAD) // wph [10][516] = 5160 f
#define OFF_X    (OFF_WPH + CC * WPH_LD)    // x_s [16][64] = 1024 f
#define OFF_WX   (OFF_X + BPG * XCHUNK)
#define OFF_BH   (OFF_WX + 64)
#define OFF_BP   (OFF_BH + 64)
#define SMEM_FLOATS (OFF_BP + 16)
#define SMEM_BYTES  (SMEM_FLOATS * 4)       // 206,816 B

__device__ float g_h[2][BB * HH];           // double-buffered hidden state (1 MB)

__device__ __forceinline__ float2 ffma2(float2 a, float2 b, float2 c)
{
    float2 d;
    asm("{\n\t"
        ".reg .b64 A,Bq,Cq;\n\t"
        "mov.b64 A, {%2,%3};\n\t"
        "mov.b64 Bq, {%4,%5};\n\t"
        "mov.b64 Cq, {%6,%7};\n\t"
        "fma.rn.f32x2 Cq, A, Bq, Cq;\n\t"
        "mov.b64 {%0,%1}, Cq;\n\t"
        "}"
        : "=f"(d.x), "=f"(d.y)
        : "f"(a.x), "f"(a.y), "f"(b.x), "f"(b.y), "f"(c.x), "f"(c.y));
    return d;
}

__device__ __forceinline__ void cluster_sync_all()
{
    asm volatile("barrier.cluster.arrive.aligned;" ::: "memory");
    asm volatile("barrier.cluster.wait.aligned;" ::: "memory");
}

__global__ void __launch_bounds__(THREADS, 1) __cluster_dims__(CPG, 1, 1)
rnn_kernel(const float* __restrict__ x,    const float* __restrict__ w_hx,
           const float* __restrict__ w_hh, const float* __restrict__ w_ph,
           const float* __restrict__ b_h,  const float* __restrict__ b_p,
           float* __restrict__ out)
{
    extern __shared__ float sm[];
    float*  w4f  = sm + OFF_W4;     // [k4][64] float4, k4-major
    float*  h_s  = sm + OFF_H;      // [16][HPAD]
    float*  red  = sm + OFF_RED;    // [4][16][RPAD]
    float*  wph  = sm + OFF_WPH;
    float*  x_s  = sm + OFF_X;      // [16][64]
    float*  wx_s = sm + OFF_WX;
    float*  bh_s = sm + OFF_BH;
    float*  bp_s = sm + OFF_BP;

    const int tid  = threadIdx.x;
    const int grp  = blockIdx.x / CPG;
    const int cta  = blockIdx.x % CPG;
    const int j0   = cta * JPC;
    const int b0   = grp * BPG;

    // ---------------- one-time staging ----------------
    for (int i = tid; i < JPC * HH; i += THREADS) {          // w_hh slice, k-quad packed
        int j = i >> 9, k = i & (HH - 1);
        w4f[(k >> 2) * 256 + j * 4 + (k & 3)] = w_hh[(j0 + j) * HH + k];
    }
    for (int i = tid; i < CC * HH; i += THREADS) {
        int c = i >> 9, j = i & (HH - 1);
        wph[c * WPH_LD + j] = w_ph[i];
    }
    if (tid < JPC) { wx_s[tid] = w_hx[j0 + tid]; bh_s[tid] = b_h[j0 + tid]; }
    if (tid < CC)  { bp_s[tid] = b_p[tid]; }
    for (int i = tid; i < BPG * HPAD; i += THREADS) h_s[i] = 0.f;   // h0 = 0
    __syncthreads();

    // warp/lane decomposition
    const int wid  = tid >> 5;
    const int lane = tid & 31;
    const int kq   = wid & 3;          // k-quarter: k4 in [kq*32, kq*32+32)
    const int bh   = wid >> 2;         // b-half: b in [bh*8, bh*8+8)
    const int bg   = lane >> 3;        // b-subgroup (2 rows each)
    const int jg   = lane & 7;         // j lane

    const int brow0 = bh * 8 + bg * 2; // first of this thread's 2 batch rows

    // hoist per-thread j constants (j = ji*8 + jg)
    float wxj[8], bhj[8];
    #pragma unroll
    for (int ji = 0; ji < 8; ++ji) { wxj[ji] = wx_s[ji * 8 + jg]; bhj[ji] = bh_s[ji * 8 + jg]; }

    const int k4beg = kq * 32;

    for (int t = 0; t < SS; ++t) {
        // ---- stage x chunk every 64 steps ----
        if ((t & (XCHUNK - 1)) == 0) {
            for (int i = tid; i < BPG * XCHUNK; i += THREADS) {
                int bb = i >> 6, tt = i & 63;
                x_s[i] = x[(b0 + bb) * SS + t + tt];
            }
            __syncthreads();
        }

        // ---- k-split GEMM: 2b x 8j tile per thread over 128 k ----
        float2 acc[2][8];
        {
            const float xv0 = x_s[(brow0 + 0) * XCHUNK + (t & 63)];
            const float xv1 = x_s[(brow0 + 1) * XCHUNK + (t & 63)];
            #pragma unroll
            for (int ji = 0; ji < 8; ++ji) {
                // bias + x contribution only once (kq==0 warps carry it)
                float base0 = (kq == 0) ? fmaf(xv0, wxj[ji], bhj[ji]) : 0.f;
                float base1 = (kq == 0) ? fmaf(xv1, wxj[ji], bhj[ji]) : 0.f;
                acc[0][ji] = make_float2(base0, 0.f);
                acc[1][ji] = make_float2(base1, 0.f);
            }
        }
        {
            const float4* hp = (const float4*)(h_s + brow0 * HPAD);
            const float4* wp = (const float4*)w4f + jg;
            #pragma unroll 2
            for (int k4 = k4beg; k4 < k4beg + 32; ++k4) {
                float4 h0 = hp[k4];
                float4 h1 = hp[k4 + HPAD / 4];
                const float4* wr = wp + k4 * 64;
                #pragma unroll
                for (int ji = 0; ji < 8; ++ji) {
                    float4 wv = wr[ji * 8];
                    acc[0][ji] = ffma2(make_float2(h0.x, h0.y), make_float2(wv.x, wv.y), acc[0][ji]);
                    acc[0][ji] = ffma2(make_float2(h0.z, h0.w), make_float2(wv.z, wv.w), acc[0][ji]);
                    acc[1][ji] = ffma2(make_float2(h1.x, h1.y), make_float2(wv.x, wv.y), acc[1][ji]);
                    acc[1][ji] = ffma2(make_float2(h1.z, h1.w), make_float2(wv.z, wv.w), acc[1][ji]);
                }
            }
        }
        __syncthreads();   // everyone done reading h_s / red free

        // ---- store k-partials to red[kq][b][j] (bank-tiled) ----
        #pragma unroll
        for (int bi = 0; bi < 2; ++bi)
            #pragma unroll
            for (int ji = 0; ji < 8; ++ji)
                red[(kq * BPG + brow0 + bi) * RPAD + ji * 8 + jg] =
                    acc[bi][ji].x + acc[bi][ji].y;
        __syncthreads();

        // ---- final reduce + tanh + publish to L2 ----
        const int p1 = (t + 1) & 1;
        float* gdst = &g_h[p1][b0 * HH + j0];
        #pragma unroll
        for (int i = 0; i < 4; ++i) {
            int o = tid + i * THREADS;           // 1024 outputs: 16b x 64j
            int b = o >> 6, j = o & 63;
            float s = red[(0 * BPG + b) * RPAD + j] + red[(1 * BPG + b) * RPAD + j]
                    + red[(2 * BPG + b) * RPAD + j] + red[(3 * BPG + b) * RPAD + j];
            s = fminf(fmaxf(s, -15.f), 15.f);
            float e  = __expf(2.f * s);
            float hn = __fdividef(e - 1.f, e + 1.f);
            __stcg(&gdst[b * HH + j], hn);
        }

        // ---- cluster barrier: release our stores, acquire peers' ----
        cluster_sync_all();

        // ---- reload full h_{t+1} (16 x 512) from L2 into padded h_s ----
        {
            const float4* src = (const float4*)&g_h[p1][b0 * HH];
            float4*       dst = (float4*)h_s;
            #pragma unroll
            for (int i = 0; i < 8; ++i) {                    // 2048 float4
                int idx = tid + i * THREADS;
                int b = idx >> 7, c4 = idx & 127;
                dst[b * (HPAD / 4) + c4] = __ldcg(src + idx);
            }
        }
        __syncthreads();

        // ---- projection for this CTA's 2 batch rows ----
        if (tid < 80) {
            int kq4 = tid / 20, rem = tid % 20;
            int bl = rem / 10, c = rem % 10;
            const float4* hrow = (const float4*)(h_s + (cta * 2 + bl) * HPAD) + kq4 * 32;
            const float4* wrow = (const float4*)(wph + c * WPH_LD) + kq4 * 32;
            float s0 = 0.f, s1 = 0.f;
            #pragma unroll 8
            for (int q = 0; q < 32; ++q) {
                float4 hv = hrow[q], wv = wrow[q];
                s0 = fmaf(hv.x, wv.x, s0); s1 = fmaf(hv.y, wv.y, s1);
                s0 = fmaf(hv.z, wv.z, s0); s1 = fmaf(hv.w, wv.w, s1);
            }
            red[tid] = s0 + s1;                  // red is free until next step's STS
        }
        __syncthreads();
        if (tid < 20) {
            int bl = tid / 10, c = tid % 10;
            float p = red[tid] + red[tid + 20] + red[tid + 40] + red[tid + 60] + bp_s[c];
            out[((b0 + cta * 2 + bl) * SS + t) * CC + c] = p;
        }
        // next iteration's red STS is fenced by the post-k-loop __syncthreads
    }
}

extern "C" void kernel_launch(void* const* d_in, const int* in_sizes, int n_in,
                              void* d_out, int out_size)
{
    const float* xx   = (const float*)d_in[0];
    const float* w_hx = (const float*)d_in[1];
    const float* w_hh = (const float*)d_in[2];
    const float* w_ph = (const float*)d_in[3];
    const float* b_h  = (const float*)d_in[4];
    const float* b_p  = (const float*)d_in[5];
    float* out = (float*)d_out;

    cudaFuncSetAttribute(rnn_kernel,
                         cudaFuncAttributeMaxDynamicSharedMemorySize, SMEM_BYTES);
    rnn_kernel<<<BB / BPG * CPG, THREADS, SMEM_BYTES>>>(xx, w_hx, w_hh, w_ph, b_h, b_p, out);
}

// round 6
// speedup vs baseline: 1.1899x; 1.1899x over previous
#include <cuda_runtime.h>

#define BB   256
#define SS   1024
#define HH   512
#define CC   10
#define GROUPS 16
#define CPG  8           // CTAs per group
#define BPG  16          // batch rows per group
#define JPC  64          // j rows per CTA
#define THREADS 256
#define K4   128         // HH/4
#define XCHUNK 64
#define HPAD 516         // padded h_s row stride (floats)
#define RPAD 68          // padded red row stride (floats)
#define WPH_LD 516

// shared memory layout (float offsets)
#define OFF_W4   0                          // [128][64] float4 = 32768 f (128 KB)
#define OFF_H    32768                      // h_s [16][516]  = 8256 f
#define OFF_RED  (OFF_H + BPG * HPAD)       // red [4][16][68] = 4352 f
#define OFF_WPH  (OFF_RED + 4 * BPG * RPAD) // wph [10][516] = 5160 f
#define OFF_X    (OFF_WPH + CC * WPH_LD)    // x_s [16][64] = 1024 f
#define OFF_WX   (OFF_X + BPG * XCHUNK)
#define OFF_BH   (OFF_WX + 64)
#define OFF_BP   (OFF_BH + 64)
#define SMEM_FLOATS (OFF_BP + 16)
#define SMEM_BYTES  (SMEM_FLOATS * 4)       // 206,816 B

__device__ float    g_h[2][BB * HH];        // double-buffered hidden state (1 MB)
__device__ unsigned g_bar[GROUPS * 32];     // per-group barrier counters (128B apart)

__device__ __forceinline__ float2 ffma2(float2 a, float2 b, float2 c)
{
    float2 d;
    asm("{\n\t"
        ".reg .b64 A,Bq,Cq;\n\t"
        "mov.b64 A, {%2,%3};\n\t"
        "mov.b64 Bq, {%4,%5};\n\t"
        "mov.b64 Cq, {%6,%7};\n\t"
        "fma.rn.f32x2 Cq, A, Bq, Cq;\n\t"
        "mov.b64 {%0,%1}, Cq;\n\t"
        "}"
        : "=f"(d.x), "=f"(d.y)
        : "f"(a.x), "f"(a.y), "f"(b.x), "f"(b.y), "f"(c.x), "f"(c.y));
    return d;
}

__global__ void zero_bar_kernel()
{
    for (int i = threadIdx.x; i < GROUPS * 32; i += blockDim.x) g_bar[i] = 0u;
}

__global__ void __launch_bounds__(THREADS, 1)
rnn_kernel(const float* __restrict__ x,    const float* __restrict__ w_hx,
           const float* __restrict__ w_hh, const float* __restrict__ w_ph,
           const float* __restrict__ b_h,  const float* __restrict__ b_p,
           float* __restrict__ out)
{
    extern __shared__ float sm[];
    float*  w4f  = sm + OFF_W4;     // [k4][64] float4, k4-major
    float*  h_s  = sm + OFF_H;      // [16][HPAD]
    float*  red  = sm + OFF_RED;    // [4][16][RPAD]
    float*  wph  = sm + OFF_WPH;
    float*  x_s  = sm + OFF_X;      // [16][64]
    float*  wx_s = sm + OFF_WX;
    float*  bh_s = sm + OFF_BH;
    float*  bp_s = sm + OFF_BP;

    const int tid  = threadIdx.x;
    const int grp  = blockIdx.x / CPG;
    const int cta  = blockIdx.x % CPG;
    const int j0   = cta * JPC;
    const int b0   = grp * BPG;

    // ---------------- one-time staging ----------------
    for (int i = tid; i < JPC * HH; i += THREADS) {          // w_hh slice, k-quad packed
        int j = i >> 9, k = i & (HH - 1);
        w4f[(k >> 2) * 256 + j * 4 + (k & 3)] = w_hh[(j0 + j) * HH + k];
    }
    for (int i = tid; i < CC * HH; i += THREADS) {
        int c = i >> 9, j = i & (HH - 1);
        wph[c * WPH_LD + j] = w_ph[i];
    }
    if (tid < JPC) { wx_s[tid] = w_hx[j0 + tid]; bh_s[tid] = b_h[j0 + tid]; }
    if (tid < CC)  { bp_s[tid] = b_p[tid]; }
    for (int i = tid; i < BPG * HPAD; i += THREADS) h_s[i] = 0.f;   // h0 = 0
    __syncthreads();

    // warp/lane decomposition
    const int wid  = tid >> 5;
    const int lane = tid & 31;
    const int kq   = wid & 3;          // k-quarter: k4 in [kq*32, kq*32+32)
    const int bhf  = wid >> 2;         // b-half: b in [bhf*8, bhf*8+8)
    const int bg   = lane >> 3;        // b-subgroup (2 rows each)
    const int jg   = lane & 7;         // j lane

    const int brow0 = bhf * 8 + bg * 2;

    float wxj[8], bhj[8];
    #pragma unroll
    for (int ji = 0; ji < 8; ++ji) { wxj[ji] = wx_s[ji * 8 + jg]; bhj[ji] = bh_s[ji * 8 + jg]; }

    const int k4beg = kq * 32;
    unsigned* bar = &g_bar[grp * 32];

    for (int t = 0; t < SS; ++t) {
        // ---- stage x chunk every 64 steps ----
        if ((t & (XCHUNK - 1)) == 0) {
            for (int i = tid; i < BPG * XCHUNK; i += THREADS) {
                int bb = i >> 6, tt = i & 63;
                x_s[i] = x[(b0 + bb) * SS + t + tt];
            }
            __syncthreads();
        }

        // ---- k-split GEMM: 2b x 8j tile per thread over 128 k ----
        float2 acc[2][8];
        {
            const float xv0 = x_s[(brow0 + 0) * XCHUNK + (t & 63)];
            const float xv1 = x_s[(brow0 + 1) * XCHUNK + (t & 63)];
            #pragma unroll
            for (int ji = 0; ji < 8; ++ji) {
                float base0 = (kq == 0) ? fmaf(xv0, wxj[ji], bhj[ji]) : 0.f;
                float base1 = (kq == 0) ? fmaf(xv1, wxj[ji], bhj[ji]) : 0.f;
                acc[0][ji] = make_float2(base0, 0.f);
                acc[1][ji] = make_float2(base1, 0.f);
            }
        }
        {
            const float4* hp = (const float4*)(h_s + brow0 * HPAD);
            const float4* wp = (const float4*)w4f + jg;
            #pragma unroll 2
            for (int k4 = k4beg; k4 < k4beg + 32; ++k4) {
                float4 h0 = hp[k4];
                float4 h1 = hp[k4 + HPAD / 4];
                const float4* wr = wp + k4 * 64;
                #pragma unroll
                for (int ji = 0; ji < 8; ++ji) {
                    float4 wv = wr[ji * 8];
                    acc[0][ji] = ffma2(make_float2(h0.x, h0.y), make_float2(wv.x, wv.y), acc[0][ji]);
                    acc[0][ji] = ffma2(make_float2(h0.z, h0.w), make_float2(wv.z, wv.w), acc[0][ji]);
                    acc[1][ji] = ffma2(make_float2(h1.x, h1.y), make_float2(wv.x, wv.y), acc[1][ji]);
                    acc[1][ji] = ffma2(make_float2(h1.z, h1.w), make_float2(wv.z, wv.w), acc[1][ji]);
                }
            }
        }

        // ---- store k-partials (red last read before previous global barrier) ----
        #pragma unroll
        for (int bi = 0; bi < 2; ++bi)
            #pragma unroll
            for (int ji = 0; ji < 8; ++ji)
                red[(kq * BPG + brow0 + bi) * RPAD + ji * 8 + jg] =
                    acc[bi][ji].x + acc[bi][ji].y;
        __syncthreads();

        // ---- final reduce + tanh + publish to L2 ----
        const int p1 = (t + 1) & 1;
        float* gdst = &g_h[p1][b0 * HH + j0];
        #pragma unroll
        for (int i = 0; i < 4; ++i) {
            int o = tid + i * THREADS;           // 1024 outputs: 16b x 64j
            int b = o >> 6, j = o & 63;
            float s = red[(0 * BPG + b) * RPAD + j] + red[(1 * BPG + b) * RPAD + j]
                    + red[(2 * BPG + b) * RPAD + j] + red[(3 * BPG + b) * RPAD + j];
            s = fminf(fmaxf(s, -15.f), 15.f);
            float e  = __expf(2.f * s);
            float hn = __fdividef(e - 1.f, e + 1.f);
            __stcg(&gdst[b * HH + j], hn);
        }

        // ---- group barrier (R2-proven: fence + monotone atomic + spin) ----
        __threadfence();
        __syncthreads();
        if (tid == 0) {
            atomicAdd(bar, 1u);
            const unsigned tgt = (unsigned)(CPG * (t + 1));
            while (*(volatile unsigned*)bar < tgt) __nanosleep(32);
            asm volatile("fence.acquire.gpu;" ::: "memory");
        }
        __syncthreads();

        // ---- reload full h_{t+1} (16 x 512) from L2 into padded h_s ----
        {
            const float4* src = (const float4*)&g_h[p1][b0 * HH];
            float4*       dst = (float4*)h_s;
            #pragma unroll
            for (int i = 0; i < 8; ++i) {                    // 2048 float4
                int idx = tid + i * THREADS;
                int b = idx >> 7, c4 = idx & 127;
                dst[b * (HPAD / 4) + c4] = __ldcg(src + idx);
            }
        }
        __syncthreads();

        // ---- projection: warps 0/1 only, shuffle reduce, NO block sync ----
        // Other warps run ahead into the next k-loop; this hides under it.
        if (wid < 2) {
            const int row = cta * 2 + wid;
            const float4* hrow = (const float4*)(h_s + row * HPAD);
            float4 hv[4];
            #pragma unroll
            for (int q = 0; q < 4; ++q) hv[q] = hrow[lane + q * 32];
            float s[CC];
            #pragma unroll
            for (int c = 0; c < CC; ++c) {
                const float4* wrow = (const float4*)(wph + c * WPH_LD);
                float a0 = 0.f, a1 = 0.f;
                #pragma unroll
                for (int q = 0; q < 4; ++q) {
                    float4 wv = wrow[lane + q * 32];
                    a0 = fmaf(hv[q].x, wv.x, a0); a1 = fmaf(hv[q].y, wv.y, a1);
                    a0 = fmaf(hv[q].z, wv.z, a0); a1 = fmaf(hv[q].w, wv.w, a1);
                }
                s[c] = a0 + a1;
                #pragma unroll
                for (int off = 16; off > 0; off >>= 1)
                    s[c] += __shfl_xor_sync(0xffffffffu, s[c], off);
            }
            if (lane == 0) {
                float* op = out + ((size_t)(b0 + row) * SS + t) * CC;
                #pragma unroll
                for (int c = 0; c < CC; ++c) op[c] = s[c] + bp_s[c];
            }
        }
    }
}

extern "C" void kernel_launch(void* const* d_in, const int* in_sizes, int n_in,
                              void* d_out, int out_size)
{
    const float* xx   = (const float*)d_in[0];
    const float* w_hx = (const float*)d_in[1];
    const float* w_hh = (const float*)d_in[2];
    const float* w_ph = (const float*)d_in[3];
    const float* b_h  = (const float*)d_in[4];
    const float* b_p  = (const float*)d_in[5];
    float* out = (float*)d_out;

    cudaFuncSetAttribute(rnn_kernel,
                         cudaFuncAttributeMaxDynamicSharedMemorySize, SMEM_BYTES);
    zero_bar_kernel<<<1, 128>>>();
    rnn_kernel<<<GROUPS * CPG, THREADS, SMEM_BYTES>>>(xx, w_hx, w_hh, w_ph, b_h, b_p, out);
}

// round 8
// speedup vs baseline: 2.3004x; 1.9333x over previous
#include <cuda_runtime.h>

#define BB   256
#define SS   1024
#define HH   512
#define CC   10
#define GROUPS 16
#define CPG  8           // CTAs per group
#define BPG  16          // batch rows per group
#define JPC  64          // j rows per CTA
#define THREADS 128
#define XCHUNK 64
#define HPAD 516         // padded h_s row stride (floats)
#define RPAD 68          // padded red row stride (floats)
#define WROW 130         // w2k row stride in floats (65 float2 = 520B)
#define WPH_LD 516

// shared memory layout (float offsets)
#define OFF_W    0                          // w2k [256 kp][130] = 33280 f (133 KB)
#define OFF_H    (256 * WROW)               // h_s [16][516] = 8256 f
#define OFF_RED  (OFF_H + BPG * HPAD)       // red [4][16][68] = 4352 f
#define OFF_WPH  (OFF_RED + 4 * BPG * RPAD) // wph [10][516] = 5160 f
#define OFF_X    (OFF_WPH + CC * WPH_LD)    // x_s [16][64] = 1024 f
#define OFF_WX   (OFF_X + BPG * XCHUNK)
#define OFF_BH   (OFF_WX + 64)
#define OFF_BP   (OFF_BH + 64)
#define SMEM_FLOATS (OFF_BP + 16)
#define SMEM_BYTES  (SMEM_FLOATS * 4)       // ~208.9 KB

__device__ float    g_h[2][BB * HH];        // double-buffered hidden state (1 MB)
__device__ unsigned g_bar[GROUPS * 32];     // per-group barrier counters

__device__ __forceinline__ float2 ffma2(float2 a, float2 b, float2 c)
{
    float2 d;
    asm("{\n\t"
        ".reg .b64 A,Bq,Cq;\n\t"
        "mov.b64 A, {%2,%3};\n\t"
        "mov.b64 Bq, {%4,%5};\n\t"
        "mov.b64 Cq, {%6,%7};\n\t"
        "fma.rn.f32x2 Cq, A, Bq, Cq;\n\t"
        "mov.b64 {%0,%1}, Cq;\n\t"
        "}"
        : "=f"(d.x), "=f"(d.y)
        : "f"(a.x), "f"(a.y), "f"(b.x), "f"(b.y), "f"(c.x), "f"(c.y));
    return d;
}

__global__ void zero_bar_kernel()
{
    for (int i = threadIdx.x; i < GROUPS * 32; i += blockDim.x) g_bar[i] = 0u;
}

__global__ void __launch_bounds__(THREADS, 1)
rnn_kernel(const float* __restrict__ x,    const float* __restrict__ w_hx,
           const float* __restrict__ w_hh, const float* __restrict__ w_ph,
           const float* __restrict__ b_h,  const float* __restrict__ b_p,
           float* __restrict__ out)
{
    extern __shared__ float sm[];
    float*  w2f  = sm + OFF_W;      // [kp][130] : float2 w2k[kp][65], [kp][j]={w[2kp][j],w[2kp+1][j]}
    float*  h_s  = sm + OFF_H;      // [16][HPAD] row-major h
    float*  red  = sm + OFF_RED;    // [4 kq][16 b][RPAD]
    float*  wph  = sm + OFF_WPH;
    float*  x_s  = sm + OFF_X;      // [16][64]
    float*  wx_s = sm + OFF_WX;
    float*  bh_s = sm + OFF_BH;
    float*  bp_s = sm + OFF_BP;

    const int tid = threadIdx.x;
    const int grp = blockIdx.x / CPG;
    const int cta = blockIdx.x % CPG;
    const int j0  = cta * JPC;
    const int b0  = grp * BPG;

    // ---------------- one-time staging ----------------
    for (int i = tid; i < JPC * HH; i += THREADS) {          // w_hh slice -> k-pair major
        int j = i >> 9, k = i & (HH - 1);
        w2f[(k >> 1) * WROW + j * 2 + (k & 1)] = w_hh[(j0 + j) * HH + k];
    }
    for (int i = tid; i < CC * HH; i += THREADS) {
        int c = i >> 9, j = i & (HH - 1);
        wph[c * WPH_LD + j] = w_ph[i];
    }
    if (tid < JPC) { wx_s[tid] = w_hx[j0 + tid]; bh_s[tid] = b_h[j0 + tid]; }
    if (tid < CC)  { bp_s[tid] = b_p[tid]; }
    for (int i = tid; i < BPG * HPAD; i += THREADS) h_s[i] = 0.f;   // h0 = 0
    __syncthreads();

    const int wid  = tid >> 5;      // warp = k-quarter
    const int lane = tid & 31;
    const int kq   = wid;

    unsigned* bar = &g_bar[grp * 32];
    const float2* w2k = (const float2*)w2f;   // index kp*65 + j

    for (int t = 0; t < SS; ++t) {
        // ---- stage x chunk every 64 steps ----
        if ((t & (XCHUNK - 1)) == 0) {
            for (int i = tid; i < BPG * XCHUNK; i += THREADS) {
                int bb = i >> 6, tt = i & 63;
                x_s[i] = x[(b0 + bb) * SS + t + tt];
            }
            __syncthreads();
        }

        // ---- k-quarter GEMM: warp covers 16b x 64j over 128 k ----
        float2 accA[16], accB[16];
        #pragma unroll
        for (int b = 0; b < 16; ++b) { accA[b] = make_float2(0.f, 0.f); accB[b] = make_float2(0.f, 0.f); }

        {
            const int k4beg = kq * 32;           // k4 index (4k per k4)
            #pragma unroll 2
            for (int k4 = k4beg; k4 < k4beg + 32; ++k4) {
                // w: 4 dense LDS.64 (lane = j), weights read once per step per CTA
                float2 wA0 = w2k[(2 * k4 + 0) * 65 + lane];
                float2 wB0 = w2k[(2 * k4 + 0) * 65 + lane + 32];
                float2 wA1 = w2k[(2 * k4 + 1) * 65 + lane];
                float2 wB1 = w2k[(2 * k4 + 1) * 65 + lane + 32];
                const float* hp = h_s + (k4 << 2);
                #pragma unroll
                for (int b = 0; b < 16; ++b) {
                    float4 hq = *(const float4*)(hp + b * HPAD);   // uniform (broadcast) load
                    float2 h01 = make_float2(hq.x, hq.y);          // native pairs, no MOV
                    float2 h23 = make_float2(hq.z, hq.w);
                    accA[b] = ffma2(h01, wA0, accA[b]);
                    accA[b] = ffma2(h23, wA1, accA[b]);
                    accB[b] = ffma2(h01, wB0, accB[b]);
                    accB[b] = ffma2(h23, wB1, accB[b]);
                }
            }
        }

        // ---- store k-partials (red free: last read before previous barrier) ----
        #pragma unroll
        for (int b = 0; b < 16; ++b) {
            red[(kq * BPG + b) * RPAD + lane]      = accA[b].x + accA[b].y;
            red[(kq * BPG + b) * RPAD + lane + 32] = accB[b].x + accB[b].y;
        }
        __syncthreads();

        // ---- final reduce (+bias +x*wx) + tanh + publish to L2 ----
        const int p1 = (t + 1) & 1;
        float* gdst = &g_h[p1][b0 * HH + j0];
        #pragma unroll
        for (int i = 0; i < 8; ++i) {
            int o = tid + i * THREADS;           // 1024 outputs: 16b x 64j
            int b = o >> 6, j = o & 63;
            float s = red[(0 * BPG + b) * RPAD + j] + red[(1 * BPG + b) * RPAD + j]
                    + red[(2 * BPG + b) * RPAD + j] + red[(3 * BPG + b) * RPAD + j];
            s += fmaf(x_s[b * XCHUNK + (t & 63)], wx_s[j], bh_s[j]);
            s = fminf(fmaxf(s, -15.f), 15.f);
            float e  = __expf(2.f * s);
            float hn = __fdividef(e - 1.f, e + 1.f);
            __stcg(&gdst[b * HH + j], hn);
        }

        // ---- group barrier (measured-best: fence + monotone atomic + spin) ----
        __threadfence();
        __syncthreads();
        if (tid == 0) {
            atomicAdd(bar, 1u);
            const unsigned tgt = (unsigned)(CPG * (t + 1));
            while (*(volatile unsigned*)bar < tgt) __nanosleep(32);
            asm volatile("fence.acquire.gpu;" ::: "memory");
        }
        __syncthreads();

        // ---- reload full h_{t+1} (16 x 512 = 2048 float4) from L2 ----
        {
            const float4* src = (const float4*)&g_h[p1][b0 * HH];
            float4*       dst = (float4*)h_s;
            #pragma unroll
            for (int i = 0; i < 16; ++i) {                   // 16 x 128 = 2048 float4
                int idx = tid + i * THREADS;
                int b = idx >> 7, c4 = idx & 127;
                dst[b * (HPAD / 4) + c4] = __ldcg(src + idx);
            }
        }
        __syncthreads();

        // ---- projection: warps 0/1 only, shuffle reduce, no block sync ----
        if (wid < 2) {
            const int row = cta * 2 + wid;
            const float4* hrow = (const float4*)(h_s + row * HPAD);
            float4 hv[4];
            #pragma unroll
            for (int q = 0; q < 4; ++q) hv[q] = hrow[lane + q * 32];
            float s[CC];
            #pragma unroll
            for (int c = 0; c < CC; ++c) {
                const float4* wrow = (const float4*)(wph + c * WPH_LD);
                float a0 = 0.f, a1 = 0.f;
                #pragma unroll
                for (int q = 0; q < 4; ++q) {
                    float4 wv = wrow[lane + q * 32];
                    a0 = fmaf(hv[q].x, wv.x, a0); a1 = fmaf(hv[q].y, wv.y, a1);
                    a0 = fmaf(hv[q].z, wv.z, a0); a1 = fmaf(hv[q].w, wv.w, a1);
                }
                s[c] = a0 + a1;
                #pragma unroll
                for (int off = 16; off > 0; off >>= 1)
                    s[c] += __shfl_xor_sync(0xffffffffu, s[c], off);
            }
            if (lane == 0) {
                float* op = out + ((size_t)(b0 + row) * SS + t) * CC;
                #pragma unroll
                for (int c = 0; c < CC; ++c) op[c] = s[c] + bp_s[c];
            }
        }
    }
}

extern "C" void kernel_launch(void* const* d_in, const int* in_sizes, int n_in,
                              void* d_out, int out_size)
{
    const float* xx   = (const float*)d_in[0];
    const float* w_hx = (const float*)d_in[1];
    const float* w_hh = (const float*)d_in[2];
    const float* w_ph = (const float*)d_in[3];
    const float* b_h  = (const float*)d_in[4];
    const float* b_p  = (const float*)d_in[5];
    float* out = (float*)d_out;

    cudaFuncSetAttribute(rnn_kernel,
                         cudaFuncAttributeMaxDynamicSharedMemorySize, SMEM_BYTES);
    zero_bar_kernel<<<1, 128>>>();
    rnn_kernel<<<GROUPS * CPG, THREADS, SMEM_BYTES>>>(xx, w_hx, w_hh, w_ph, b_h, b_p, out);
}

// round 9
// speedup vs baseline: 2.4706x; 1.0740x over previous
#include <cuda_runtime.h>

#define BB   256
#define SS   1024
#define HH   512
#define CC   10
#define GROUPS 16
#define CPG  8           // CTAs per group
#define BPG  16          // batch rows per group
#define JPC  64          // j rows per CTA
#define THREADS 256
#define NWARP 8
#define XCHUNK 64
#define HPAD 516         // padded h_s row stride (floats)
#define RPAD 64          // red row stride (floats) — conflict-free both phases
#define WROW 130         // w2k row stride in floats (65 float2 = 520B)
#define WPH_LD 516

// shared memory layout (float offsets)
#define OFF_W    0                              // w2k [256 kp][130] = 33280 f
#define OFF_H    (256 * WROW)                   // h_s [16][516] = 8256 f
#define OFF_RED  (OFF_H + BPG * HPAD)           // red [8][16][64] = 8192 f
#define OFF_WPH  (OFF_RED + NWARP * BPG * RPAD) // wph [10][516] = 5160 f
#define OFF_X    (OFF_WPH + CC * WPH_LD)        // x_s [16][64] = 1024 f
#define OFF_WX   (OFF_X + BPG * XCHUNK)
#define OFF_BH   (OFF_WX + 64)
#define OFF_BP   (OFF_BH + 64)
#define SMEM_FLOATS (OFF_BP + 16)
#define SMEM_BYTES  (SMEM_FLOATS * 4)           // 224,224 B

__device__ float    g_h[2][BB * HH];        // double-buffered hidden state (1 MB)
__device__ unsigned g_bar[GROUPS * 32];     // per-group barrier counters

__device__ __forceinline__ float2 ffma2(float2 a, float2 b, float2 c)
{
    float2 d;
    asm("{\n\t"
        ".reg .b64 A,Bq,Cq;\n\t"
        "mov.b64 A, {%2,%3};\n\t"
        "mov.b64 Bq, {%4,%5};\n\t"
        "mov.b64 Cq, {%6,%7};\n\t"
        "fma.rn.f32x2 Cq, A, Bq, Cq;\n\t"
        "mov.b64 {%0,%1}, Cq;\n\t"
        "}"
        : "=f"(d.x), "=f"(d.y)
        : "f"(a.x), "f"(a.y), "f"(b.x), "f"(b.y), "f"(c.x), "f"(c.y));
    return d;
}

__device__ __forceinline__ void bar_release_add(unsigned* p)
{
    asm volatile("red.release.gpu.global.add.u32 [%0], 1;" :: "l"(p) : "memory");
}
__device__ __forceinline__ unsigned bar_acquire_ld(const unsigned* p)
{
    unsigned v;
    asm volatile("ld.acquire.gpu.global.u32 %0, [%1];" : "=r"(v) : "l"(p) : "memory");
    return v;
}

__global__ void zero_bar_kernel()
{
    for (int i = threadIdx.x; i < GROUPS * 32; i += blockDim.x) g_bar[i] = 0u;
}

__global__ void __launch_bounds__(THREADS, 1)
rnn_kernel(const float* __restrict__ x,    const float* __restrict__ w_hx,
           const float* __restrict__ w_hh, const float* __restrict__ w_ph,
           const float* __restrict__ b_h,  const float* __restrict__ b_p,
           float* __restrict__ out)
{
    extern __shared__ float sm[];
    float*  w2f  = sm + OFF_W;      // [kp][130] : float2 w2k[kp][65]
    float*  h_s  = sm + OFF_H;      // [16][HPAD]
    float*  red  = sm + OFF_RED;    // [8 kw][16 b][RPAD]
    float*  wph  = sm + OFF_WPH;
    float*  x_s  = sm + OFF_X;      // [16][64]
    float*  wx_s = sm + OFF_WX;
    float*  bh_s = sm + OFF_BH;
    float*  bp_s = sm + OFF_BP;

    const int tid = threadIdx.x;
    const int grp = blockIdx.x / CPG;
    const int cta = blockIdx.x % CPG;
    const int j0  = cta * JPC;
    const int b0  = grp * BPG;

    // ---------------- one-time staging ----------------
    for (int i = tid; i < JPC * HH; i += THREADS) {          // w_hh slice -> k-pair major
        int j = i >> 9, k = i & (HH - 1);
        w2f[(k >> 1) * WROW + j * 2 + (k & 1)] = w_hh[(j0 + j) * HH + k];
    }
    for (int i = tid; i < CC * HH; i += THREADS) {
        int c = i >> 9, j = i & (HH - 1);
        wph[c * WPH_LD + j] = w_ph[i];
    }
    if (tid < JPC) { wx_s[tid] = w_hx[j0 + tid]; bh_s[tid] = b_h[j0 + tid]; }
    if (tid < CC)  { bp_s[tid] = b_p[tid]; }
    for (int i = tid; i < BPG * HPAD; i += THREADS) h_s[i] = 0.f;   // h0 = 0
    __syncthreads();

    const int wid  = tid >> 5;      // warp = k-eighth
    const int lane = tid & 31;
    const int kw   = wid;

    unsigned* bar = &g_bar[grp * 32];
    const float2* w2k = (const float2*)w2f;   // index kp*65 + j

    for (int t = 0; t < SS; ++t) {
        // ---- stage x chunk every 64 steps ----
        if ((t & (XCHUNK - 1)) == 0) {
            for (int i = tid; i < BPG * XCHUNK; i += THREADS) {
                int bb = i >> 6, tt = i & 63;
                x_s[i] = x[(b0 + bb) * SS + t + tt];
            }
            __syncthreads();
        }

        // ---- k-eighth GEMM: warp covers 16b x 64j over 64 k ----
        float2 accA[16], accB[16];
        #pragma unroll
        for (int b = 0; b < 16; ++b) { accA[b] = make_float2(0.f, 0.f); accB[b] = make_float2(0.f, 0.f); }

        {
            const int k4beg = kw * 16;           // 16 k4 per warp (4k per k4)
            #pragma unroll 2
            for (int k4 = k4beg; k4 < k4beg + 16; ++k4) {
                float2 wA0 = w2k[(2 * k4 + 0) * 65 + lane];
                float2 wB0 = w2k[(2 * k4 + 0) * 65 + lane + 32];
                float2 wA1 = w2k[(2 * k4 + 1) * 65 + lane];
                float2 wB1 = w2k[(2 * k4 + 1) * 65 + lane + 32];
                const float* hp = h_s + (k4 << 2);
                #pragma unroll
                for (int b = 0; b < 16; ++b) {
                    float4 hq = *(const float4*)(hp + b * HPAD);   // uniform broadcast
                    float2 h01 = make_float2(hq.x, hq.y);
                    float2 h23 = make_float2(hq.z, hq.w);
                    accA[b] = ffma2(h01, wA0, accA[b]);
                    accA[b] = ffma2(h23, wA1, accA[b]);
                    accB[b] = ffma2(h01, wB0, accB[b]);
                    accB[b] = ffma2(h23, wB1, accB[b]);
                }
            }
        }

        // ---- store k-partials ----
        #pragma unroll
        for (int b = 0; b < 16; ++b) {
            red[(kw * BPG + b) * RPAD + lane]      = accA[b].x + accA[b].y;
            red[(kw * BPG + b) * RPAD + lane + 32] = accB[b].x + accB[b].y;
        }
        __syncthreads();

        // ---- final reduce (+bias +x*wx) + tanh + publish to L2 ----
        const int p1 = (t + 1) & 1;
        float* gdst = &g_h[p1][b0 * HH + j0];
        #pragma unroll
        for (int i = 0; i < 4; ++i) {
            int o = tid + i * THREADS;           // 1024 outputs: 16b x 64j
            int b = o >> 6, j = o & 63;
            const float* rp = red + b * RPAD + j;
            float s01 = rp[0 * BPG * RPAD] + rp[1 * BPG * RPAD];
            float s23 = rp[2 * BPG * RPAD] + rp[3 * BPG * RPAD];
            float s45 = rp[4 * BPG * RPAD] + rp[5 * BPG * RPAD];
            float s67 = rp[6 * BPG * RPAD] + rp[7 * BPG * RPAD];
            float s = (s01 + s23) + (s45 + s67)
                    + fmaf(x_s[b * XCHUNK + (t & 63)], wx_s[j], bh_s[j]);
            s = fminf(fmaxf(s, -15.f), 15.f);
            float e  = __expf(2.f * s);
            float hn = __fdividef(e - 1.f, e + 1.f);
            __stcg(&gdst[b * HH + j], hn);
        }

        // ---- group barrier: sync + release-red + acquire-spin (no membar drain) ----
        __syncthreads();
        if (tid == 0) {
            bar_release_add(bar);
            const unsigned tgt = (unsigned)(CPG * (t + 1));
            while (bar_acquire_ld(bar) < tgt) __nanosleep(32);
        }
        __syncthreads();

        // ---- reload full h_{t+1} (16 x 512 = 2048 float4) from L2 ----
        {
            const float4* src = (const float4*)&g_h[p1][b0 * HH];
            float4*       dst = (float4*)h_s;
            #pragma unroll
            for (int i = 0; i < 8; ++i) {                    // 8 x 256 = 2048 float4
                int idx = tid + i * THREADS;
                int b = idx >> 7, c4 = idx & 127;
                dst[b * (HPAD / 4) + c4] = __ldcg(src + idx);
            }
        }
        __syncthreads();

        // ---- projection: warps 0/1 only, shuffle reduce, no block sync ----
        if (wid < 2) {
            const int row = cta * 2 + wid;
            const float4* hrow = (const float4*)(h_s + row * HPAD);
            float4 hv[4];
            #pragma unroll
            for (int q = 0; q < 4; ++q) hv[q] = hrow[lane + q * 32];
            float s[CC];
            #pragma unroll
            for (int c = 0; c < CC; ++c) {
                const float4* wrow = (const float4*)(wph + c * WPH_LD);
                float a0 = 0.f, a1 = 0.f;
                #pragma unroll
                for (int q = 0; q < 4; ++q) {
                    float4 wv = wrow[lane + q * 32];
                    a0 = fmaf(hv[q].x, wv.x, a0); a1 = fmaf(hv[q].y, wv.y, a1);
                    a0 = fmaf(hv[q].z, wv.z, a0); a1 = fmaf(hv[q].w, wv.w, a1);
                }
                s[c] = a0 + a1;
                #pragma unroll
                for (int off = 16; off > 0; off >>= 1)
                    s[c] += __shfl_xor_sync(0xffffffffu, s[c], off);
            }
            if (lane == 0) {
                float* op = out + ((size_t)(b0 + row) * SS + t) * CC;
                #pragma unroll
                for (int c = 0; c < CC; ++c) op[c] = s[c] + bp_s[c];
            }
        }
    }
}

extern "C" void kernel_launch(void* const* d_in, const int* in_sizes, int n_in,
                              void* d_out, int out_size)
{
    const float* xx   = (const float*)d_in[0];
    const float* w_hx = (const float*)d_in[1];
    const float* w_hh = (const float*)d_in[2];
    const float* w_ph = (const float*)d_in[3];
    const float* b_h  = (const float*)d_in[4];
    const float* b_p  = (const float*)d_in[5];
    float* out = (float*)d_out;

    cudaFuncSetAttribute(rnn_kernel,
                         cudaFuncAttributeMaxDynamicSharedMemorySize, SMEM_BYTES);
    zero_bar_kernel<<<1, 128>>>();
    rnn_kernel<<<GROUPS * CPG, THREADS, SMEM_BYTES>>>(xx, w_hx, w_hh, w_ph, b_h, b_p, out);
}